// round 9
// baseline (speedup 1.0000x reference)
#include <cuda_runtime.h>
#include <cstdint>

#define TT   512
#define BB   1024
#define H1   64
#define G1   256     // 4*H1
#define BT1  8
#define H2   32
#define G2   128     // 4*H2

typedef unsigned long long ull;

// scratch: h1[t][b][j], j in [0,128): fwd half [0,64), rev half [64,128)
__device__ float g_h1[(size_t)TT * BB * 128];
// precomputed layer-2 input projection + bias: xi[t][b][g], g in [0,128)
__device__ float g_xi[(size_t)TT * BB * 128];

// ---- fast activations -----------------------------------------------------
__device__ __forceinline__ float tanh_(float x) {
    float y;
    asm("tanh.approx.f32 %0, %1;" : "=f"(y) : "f"(x));
    return y;
}
__device__ __forceinline__ float sigm(float x) {
    return fmaf(tanh_(x * 0.5f), 0.5f, 0.5f);
}

// ---- packed fp32x2 fma ----------------------------------------------------
__device__ __forceinline__ void ffma2(ull& acc, ull a, ull b) {
    asm("fma.rn.f32x2 %0, %1, %2, %0;" : "+l"(acc) : "l"(a), "l"(b));
}
__device__ __forceinline__ ull pack2(float lo, float hi) {
    ull r;
    asm("mov.b64 %0, {%1, %2};" : "=l"(r) : "f"(lo), "f"(hi));
    return r;
}
__device__ __forceinline__ float hadd2(ull v) {
    float lo, hi;
    asm("mov.b64 {%0, %1}, %2;" : "=f"(lo), "=f"(hi) : "l"(v));
    return lo + hi;
}
__device__ __forceinline__ void unpk(ull v, float& lo, float& hi) {
    asm("mov.b64 {%0, %1}, %2;" : "=f"(lo), "=f"(hi) : "l"(v));
}

// ---------------------------------------------------------------------------
// Kernel 1: bidirectional layer-1 LSTM (unchanged — best known).
// grid = (128, 2), block = 256.  thread = (gp = tid&127, half = tid>>7).
// ---------------------------------------------------------------------------
__global__ __launch_bounds__(256, 2)
void lstm1_kernel(const float* __restrict__ x,
                  const float* __restrict__ wih_f, const float* __restrict__ whh_f,
                  const float* __restrict__ b_f,
                  const float* __restrict__ wih_r, const float* __restrict__ whh_r,
                  const float* __restrict__ b_r)
{
    const int dir  = blockIdx.y;
    const int b0   = blockIdx.x * BT1;
    const int tid  = threadIdx.x;
    const int gp   = tid & 127;
    const int half = tid >> 7;

    const float* wih = dir ? wih_r : wih_f;
    const float* whh = dir ? whh_r : whh_f;
    const float* bb  = dir ? b_r  : b_f;

    __shared__ float sxc[BT1][64];
    __shared__ float sh[BT1][H1];
    __shared__ float szA[BT1][G1];
    __shared__ float szB[BT1][G1];

    for (int i = tid; i < BT1 * H1; i += 256) ((float*)sh)[i] = 0.f;

    ull wp0[16], wp1[16];
    {
        const ull* w0 = (const ull*)(whh + (2 * gp)     * H1 + 32 * half);
        const ull* w1 = (const ull*)(whh + (2 * gp + 1) * H1 + 32 * half);
#pragma unroll
        for (int j = 0; j < 16; j++) { wp0[j] = w0[j]; wp1[j] = w1[j]; }
    }
    const float wi0 = (half == 0) ? wih[2 * gp]     : 0.f;
    const float wi1 = (half == 0) ? wih[2 * gp + 1] : 0.f;
    const float bg0 = (half == 0) ? bb[2 * gp]      : 0.f;
    const float bg1 = (half == 0) ? bb[2 * gp + 1]  : 0.f;

    float c0 = 0.f, c1 = 0.f;
    const int cb = tid >> 6;
    const int ch = tid & 63;

    float* dst = half ? &szB[0][0] : &szA[0][0];

    __syncthreads();

    for (int tt = 0; tt < TT; ++tt) {
        const int t = dir ? (TT - 1 - tt) : tt;

        if ((tt & 63) == 0) {
            const int tbase = dir ? (448 - tt) : tt;
            for (int i = tid; i < BT1 * 64; i += 256) {
                int b = i >> 6, to = i & 63;
                sxc[b][to] = x[(size_t)(b0 + b) * TT + tbase + to];
            }
            __syncthreads();
        }
        const int ts = t & 63;

        // P1: cell(B, t-1) + FMA(A, t)
        if (tt > 0) {
            const int tp  = dir ? (TT - tt) : (tt - 1);
            const int cb2 = cb + 4;
            float zi = szA[cb2][ch]       + szB[cb2][ch];
            float zf = szA[cb2][64 + ch]  + szB[cb2][64 + ch];
            float zg = szA[cb2][128 + ch] + szB[cb2][128 + ch];
            float zo = szA[cb2][192 + ch] + szB[cb2][192 + ch];
            c1 = sigm(zf) * c1 + sigm(zi) * tanh_(zg);
            float hv = sigm(zo) * tanh_(c1);
            sh[cb2][ch] = hv;
            g_h1[((size_t)tp * BB + (b0 + cb2)) * 128 + dir * 64 + ch] = hv;
        }
        {
            ull a0[4], a1[4];
            if (half == 0) {
#pragma unroll
                for (int b = 0; b < 4; b++) {
                    float xv = sxc[b][ts];
                    a0[b] = pack2(fmaf(xv, wi0, bg0), 0.f);
                    a1[b] = pack2(fmaf(xv, wi1, bg1), 0.f);
                }
            } else {
#pragma unroll
                for (int b = 0; b < 4; b++) { a0[b] = 0ULL; a1[b] = 0ULL; }
            }
#pragma unroll
            for (int j = 0; j < 8; j++) {
#pragma unroll
                for (int b = 0; b < 4; b++) {
                    ulonglong2 hv = *(const ulonglong2*)&sh[b][32 * half + 4 * j];
                    ffma2(a0[b], hv.x, wp0[2 * j]);
                    ffma2(a0[b], hv.y, wp0[2 * j + 1]);
                    ffma2(a1[b], hv.x, wp1[2 * j]);
                    ffma2(a1[b], hv.y, wp1[2 * j + 1]);
                }
            }
#pragma unroll
            for (int b = 0; b < 4; b++)
                *(ull*)(dst + b * G1 + 2 * gp) = pack2(hadd2(a0[b]), hadd2(a1[b]));
        }
        __syncthreads();

        // P2: cell(A, t) + FMA(B, t)
        {
            float zi = szA[cb][ch]       + szB[cb][ch];
            float zf = szA[cb][64 + ch]  + szB[cb][64 + ch];
            float zg = szA[cb][128 + ch] + szB[cb][128 + ch];
            float zo = szA[cb][192 + ch] + szB[cb][192 + ch];
            c0 = sigm(zf) * c0 + sigm(zi) * tanh_(zg);
            float hv = sigm(zo) * tanh_(c0);
            sh[cb][ch] = hv;
            g_h1[((size_t)t * BB + (b0 + cb)) * 128 + dir * 64 + ch] = hv;
        }
        {
            ull a0[4], a1[4];
            if (half == 0) {
#pragma unroll
                for (int b = 0; b < 4; b++) {
                    float xv = sxc[b + 4][ts];
                    a0[b] = pack2(fmaf(xv, wi0, bg0), 0.f);
                    a1[b] = pack2(fmaf(xv, wi1, bg1), 0.f);
                }
            } else {
#pragma unroll
                for (int b = 0; b < 4; b++) { a0[b] = 0ULL; a1[b] = 0ULL; }
            }
#pragma unroll
            for (int j = 0; j < 8; j++) {
#pragma unroll
                for (int b = 0; b < 4; b++) {
                    ulonglong2 hv = *(const ulonglong2*)&sh[b + 4][32 * half + 4 * j];
                    ffma2(a0[b], hv.x, wp0[2 * j]);
                    ffma2(a0[b], hv.y, wp0[2 * j + 1]);
                    ffma2(a1[b], hv.x, wp1[2 * j]);
                    ffma2(a1[b], hv.y, wp1[2 * j + 1]);
                }
            }
#pragma unroll
            for (int b = 0; b < 4; b++)
                *(ull*)(dst + (b + 4) * G1 + 2 * gp) = pack2(hadd2(a0[b]), hadd2(a1[b]));
        }
        __syncthreads();
    }

    {
        const int tp  = dir ? 0 : (TT - 1);
        const int cb2 = cb + 4;
        float zi = szA[cb2][ch]       + szB[cb2][ch];
        float zf = szA[cb2][64 + ch]  + szB[cb2][64 + ch];
        float zg = szA[cb2][128 + ch] + szB[cb2][128 + ch];
        float zo = szA[cb2][192 + ch] + szB[cb2][192 + ch];
        c1 = sigm(zf) * c1 + sigm(zi) * tanh_(zg);
        float hv = sigm(zo) * tanh_(c1);
        g_h1[((size_t)tp * BB + (b0 + cb2)) * 128 + dir * 64 + ch] = hv;
    }
}

// ---------------------------------------------------------------------------
// Kernel 2: xi = h1 @ Wih2f^T + b2f.   M = TT*BB, N = 128, K = 128.
// grid = 4096, block = 256.  Tile 128m x 128n; k-chunks of 8, double-buffered.
// Smem pre-paired: As[k][m] floats (LDS.128 = 2 m-pairs), Ws[k][n] dup-ull
// (LDS.128 = 2 ready n-broadcast operands).  Inner loop: 6 LDS.128 + 32 FFMA2.
// ---------------------------------------------------------------------------
#define KC 8
__global__ __launch_bounds__(256, 2)
void xi_gemm_kernel(const float* __restrict__ W,     // wih2f [128][128]
                    const float* __restrict__ bias)  // b2f [128]
{
    const int tid   = threadIdx.x;
    const int mbase = blockIdx.x * 128;
    const int ni    = tid & 15;
    const int mi    = tid >> 4;
    const int n0    = ni * 8;
    const int m0    = mi * 8;

    __shared__ float As[2][KC][128];   // 2 x 4 KB
    __shared__ ull   Ws[2][KC][128];   // 2 x 8 KB (duplicated weights)

    // accumulators: 4 m-pairs x 8 n
    ull acc[4][8];
#pragma unroll
    for (int n = 0; n < 8; n++) {
        float bv = bias[n0 + n];
#pragma unroll
        for (int mp = 0; mp < 4; mp++) acc[mp][n] = pack2(bv, bv);
    }

    const int lr = tid & 127;       // row (m or n) this thread stages
    const int kq = tid >> 7;        // k-quad: 0 -> k 0..3, 1 -> k 4..7

    // prologue: stage chunk 0
    {
        float4 av = *(const float4*)(g_h1 + (size_t)(mbase + lr) * 128 + 4 * kq);
        As[0][4 * kq + 0][lr] = av.x;
        As[0][4 * kq + 1][lr] = av.y;
        As[0][4 * kq + 2][lr] = av.z;
        As[0][4 * kq + 3][lr] = av.w;
        float4 wv = *(const float4*)(W + lr * 128 + 4 * kq);
        Ws[0][4 * kq + 0][lr] = pack2(wv.x, wv.x);
        Ws[0][4 * kq + 1][lr] = pack2(wv.y, wv.y);
        Ws[0][4 * kq + 2][lr] = pack2(wv.z, wv.z);
        Ws[0][4 * kq + 3][lr] = pack2(wv.w, wv.w);
    }
    __syncthreads();

    for (int ch = 0; ch < 128 / KC; ++ch) {
        const int cur = ch & 1;

        // issue staging loads for next chunk (hidden under compute)
        float4 av, wv;
        const bool more = (ch + 1 < 128 / KC);
        if (more) {
            const int kc = (ch + 1) * KC;
            av = *(const float4*)(g_h1 + (size_t)(mbase + lr) * 128 + kc + 4 * kq);
            wv = *(const float4*)(W + lr * 128 + kc + 4 * kq);
        }

        // compute on current chunk
#pragma unroll
        for (int k = 0; k < KC; k++) {
            ulonglong2 a01 = *(const ulonglong2*)&As[cur][k][m0];
            ulonglong2 a23 = *(const ulonglong2*)&As[cur][k][m0 + 4];
            ulonglong2 w01 = *(const ulonglong2*)&Ws[cur][k][n0];
            ulonglong2 w23 = *(const ulonglong2*)&Ws[cur][k][n0 + 2];
            ulonglong2 w45 = *(const ulonglong2*)&Ws[cur][k][n0 + 4];
            ulonglong2 w67 = *(const ulonglong2*)&Ws[cur][k][n0 + 6];
            ull ap[4] = {a01.x, a01.y, a23.x, a23.y};
            ull wd[8] = {w01.x, w01.y, w23.x, w23.y, w45.x, w45.y, w67.x, w67.y};
#pragma unroll
            for (int n = 0; n < 8; n++)
#pragma unroll
                for (int mp = 0; mp < 4; mp++) ffma2(acc[mp][n], ap[mp], wd[n]);
        }

        // park staged data in the other buffer
        if (more) {
            const int nxt = 1 - cur;
            As[nxt][4 * kq + 0][lr] = av.x;
            As[nxt][4 * kq + 1][lr] = av.y;
            As[nxt][4 * kq + 2][lr] = av.z;
            As[nxt][4 * kq + 3][lr] = av.w;
            Ws[nxt][4 * kq + 0][lr] = pack2(wv.x, wv.x);
            Ws[nxt][4 * kq + 1][lr] = pack2(wv.y, wv.y);
            Ws[nxt][4 * kq + 2][lr] = pack2(wv.z, wv.z);
            Ws[nxt][4 * kq + 3][lr] = pack2(wv.w, wv.w);
        }
        __syncthreads();
    }

    // write back: rows m0+2mp, m0+2mp+1; 8 consecutive n each
#pragma unroll
    for (int mp = 0; mp < 4; mp++) {
        float r0[8], r1[8];
#pragma unroll
        for (int n = 0; n < 8; n++) unpk(acc[mp][n], r0[n], r1[n]);
        float* d0 = g_xi + (size_t)(mbase + m0 + 2 * mp) * 128 + n0;
        float* d1 = d0 + 128;
        *(float4*)(d0)     = make_float4(r0[0], r0[1], r0[2], r0[3]);
        *(float4*)(d0 + 4) = make_float4(r0[4], r0[5], r0[6], r0[7]);
        *(float4*)(d1)     = make_float4(r1[0], r1[1], r1[2], r1[3]);
        *(float4*)(d1 + 4) = make_float4(r1[4], r1[5], r1[6], r1[7]);
    }
}

// ---------------------------------------------------------------------------
// Kernel 3: layer-2 recurrent scan (warp per batch, no block barriers in loop)
// + single reverse step + MLP head.  (unchanged)
// ---------------------------------------------------------------------------
__global__ __launch_bounds__(256, 1)
void lstm2_scan_kernel(const float* __restrict__ whh2f,
                       const float* __restrict__ wih2r, const float* __restrict__ b2r,
                       const float* __restrict__ w_fc1, const float* __restrict__ b_fc1,
                       const float* __restrict__ w_out, const float* __restrict__ b_out,
                       float* __restrict__ out)
{
    const int b0  = blockIdx.x * 8;
    const int tid = threadIdx.x;
    const int w   = tid >> 5;
    const int j   = tid & 31;
    const int bb  = b0 + w;

    __shared__ float shh[8][32];
    __shared__ float h1last[8][128];
    __shared__ float zrev[8][128];
    __shared__ float slast[8][64];
    __shared__ float sfc[8][64];

    ull wq[4][16];
#pragma unroll
    for (int q = 0; q < 4; q++) {
        const ull* wr = (const ull*)(whh2f + (q * 32 + j) * H2);
#pragma unroll
        for (int p = 0; p < 16; p++) wq[q][p] = wr[p];
    }

    shh[w][j] = 0.f;
    float c = 0.f, hmine = 0.f;

    const float* xibase = g_xi + (size_t)bb * 128 + j;
    float xin[4];
#pragma unroll
    for (int q = 0; q < 4; q++) xin[q] = xibase[q * 32];

    __syncwarp();

    for (int t = 0; t < TT; ++t) {
        float xnx[4] = {0.f, 0.f, 0.f, 0.f};
        if (t + 1 < TT) {
            const float* p = xibase + (size_t)(t + 1) * BB * 128;
#pragma unroll
            for (int q = 0; q < 4; q++) xnx[q] = p[q * 32];
        }

        ull acc[4];
#pragma unroll
        for (int q = 0; q < 4; q++) acc[q] = pack2(xin[q], 0.f);

#pragma unroll
        for (int p = 0; p < 16; p++) {
            ull hv = *(const ull*)&shh[w][2 * p];
#pragma unroll
            for (int q = 0; q < 4; q++) ffma2(acc[q], hv, wq[q][p]);
        }
        float zi = hadd2(acc[0]);
        float zf = hadd2(acc[1]);
        float zg = hadd2(acc[2]);
        float zo = hadd2(acc[3]);
        c = sigm(zf) * c + sigm(zi) * tanh_(zg);
        hmine = sigm(zo) * tanh_(c);

        __syncwarp();
        shh[w][j] = hmine;
        __syncwarp();

#pragma unroll
        for (int q = 0; q < 4; q++) xin[q] = xnx[q];
    }

    __syncthreads();

    {
        int idx = tid * 4;
        int b = idx >> 7, k = idx & 127;
        *(float4*)&h1last[b][k] =
            *(const float4*)(g_h1 + ((size_t)(TT - 1) * BB + b0 + b) * 128 + k);
    }
    __syncthreads();

    {
        const int g2 = tid & 127;
        const int hf = tid >> 7;
        const float brv = b2r[g2];
        float a[4] = {brv, brv, brv, brv};
        const float* wr = wih2r + g2 * G2;
        for (int k = 0; k < G2; k++) {
            float wv = __ldg(wr + k);
#pragma unroll
            for (int b = 0; b < 4; b++)
                a[b] = fmaf(h1last[hf * 4 + b][k], wv, a[b]);
        }
#pragma unroll
        for (int b = 0; b < 4; b++) zrev[hf * 4 + b][g2] = a[b];
    }
    __syncthreads();
    {
        const int b = tid >> 5, jj = tid & 31;
        float zi = zrev[b][jj];
        float zg = zrev[b][64 + jj], zo = zrev[b][96 + jj];
        float cr = sigm(zi) * tanh_(zg);
        float hr = sigm(zo) * tanh_(cr);
        slast[b][jj]      = shh[b][jj];
        slast[b][32 + jj] = hr;
    }
    __syncthreads();

#pragma unroll
    for (int rep = 0; rep < 2; rep++) {
        int item = tid + rep * 256;
        int b = item >> 6, o = item & 63;
        float a = b_fc1[o];
        const float* wf = w_fc1 + o * 64;
        for (int k = 0; k < 64; k++) a = fmaf(slast[b][k], __ldg(wf + k), a);
        sfc[b][o] = fmaxf(a, 0.f);
    }
    __syncthreads();

    if (tid < 8) {
        float a = b_out[0];
        for (int k = 0; k < 64; k++) a = fmaf(sfc[tid][k], __ldg(w_out + k), a);
        out[b0 + tid] = sigm(a);
    }
}

// ---------------------------------------------------------------------------
extern "C" void kernel_launch(void* const* d_in, const int* in_sizes, int n_in,
                              void* d_out, int out_size)
{
    (void)in_sizes; (void)n_in; (void)out_size;
    const float* x     = (const float*)d_in[0];
    const float* wih1f = (const float*)d_in[1];
    const float* whh1f = (const float*)d_in[2];
    const float* b1f   = (const float*)d_in[3];
    const float* wih1r = (const float*)d_in[4];
    const float* whh1r = (const float*)d_in[5];
    const float* b1r   = (const float*)d_in[6];
    const float* wih2f = (const float*)d_in[7];
    const float* whh2f = (const float*)d_in[8];
    const float* b2f   = (const float*)d_in[9];
    const float* wih2r = (const float*)d_in[10];
    const float* b2r   = (const float*)d_in[12];
    const float* w_fc1 = (const float*)d_in[13];
    const float* b_fc1 = (const float*)d_in[14];
    const float* w_out = (const float*)d_in[15];
    const float* b_out = (const float*)d_in[16];
    float* out = (float*)d_out;

    lstm1_kernel<<<dim3(BB / BT1, 2), 256>>>(x, wih1f, whh1f, b1f, wih1r, whh1r, b1r);
    xi_gemm_kernel<<<(TT * BB) / 128, 256>>>(wih2f, b2f);
    lstm2_scan_kernel<<<BB / 8, 256>>>(whh2f, wih2r, b2r,
                                       w_fc1, b_fc1, w_out, b_out, out);
}

// round 10
// speedup vs baseline: 1.5994x; 1.5994x over previous
#include <cuda_runtime.h>
#include <cstdint>

#define TT   512
#define BB   1024
#define H1   64
#define G1   256     // 4*H1
#define BT1  8
#define H2   32
#define G2   128     // 4*H2

typedef unsigned long long ull;

// scratch: h1[t][b][j], j in [0,128): fwd half [0,64), rev half [64,128)
__device__ float g_h1[(size_t)TT * BB * 128];
// precomputed layer-2 input projection + bias: xi[t][b][g], g in [0,128)
__device__ float g_xi[(size_t)TT * BB * 128];

// ---- fast activations -----------------------------------------------------
__device__ __forceinline__ float tanh_(float x) {
    float y;
    asm("tanh.approx.f32 %0, %1;" : "=f"(y) : "f"(x));
    return y;
}
__device__ __forceinline__ float sigm(float x) {
    return fmaf(tanh_(x * 0.5f), 0.5f, 0.5f);
}

// ---- packed fp32x2 fma ----------------------------------------------------
__device__ __forceinline__ void ffma2(ull& acc, ull a, ull b) {
    asm("fma.rn.f32x2 %0, %1, %2, %0;" : "+l"(acc) : "l"(a), "l"(b));
}
__device__ __forceinline__ ull pack2(float lo, float hi) {
    ull r;
    asm("mov.b64 %0, {%1, %2};" : "=l"(r) : "f"(lo), "f"(hi));
    return r;
}
__device__ __forceinline__ float hadd2(ull v) {
    float lo, hi;
    asm("mov.b64 {%0, %1}, %2;" : "=f"(lo), "=f"(hi) : "l"(v));
    return lo + hi;
}

// ---- tf32 helpers -----------------------------------------------------------
__device__ __forceinline__ uint32_t to_tf32(float x) {
    uint32_t r;
    asm("cvt.rna.tf32.f32 %0, %1;" : "=r"(r) : "f"(x));
    return r;
}
__device__ __forceinline__ void mma_tf32(float& c0, float& c1, float& c2, float& c3,
                                         uint32_t a0, uint32_t a1, uint32_t a2, uint32_t a3,
                                         uint32_t b0, uint32_t b1) {
    asm("mma.sync.aligned.m16n8k8.row.col.f32.tf32.tf32.f32 "
        "{%0,%1,%2,%3}, {%4,%5,%6,%7}, {%8,%9}, {%0,%1,%2,%3};"
        : "+f"(c0), "+f"(c1), "+f"(c2), "+f"(c3)
        : "r"(a0), "r"(a1), "r"(a2), "r"(a3), "r"(b0), "r"(b1));
}

// ---------------------------------------------------------------------------
// Kernel 1: bidirectional layer-1 LSTM (unchanged — best known).
// grid = (128, 2), block = 256.  thread = (gp = tid&127, half = tid>>7).
// ---------------------------------------------------------------------------
__global__ __launch_bounds__(256, 2)
void lstm1_kernel(const float* __restrict__ x,
                  const float* __restrict__ wih_f, const float* __restrict__ whh_f,
                  const float* __restrict__ b_f,
                  const float* __restrict__ wih_r, const float* __restrict__ whh_r,
                  const float* __restrict__ b_r)
{
    const int dir  = blockIdx.y;
    const int b0   = blockIdx.x * BT1;
    const int tid  = threadIdx.x;
    const int gp   = tid & 127;
    const int half = tid >> 7;

    const float* wih = dir ? wih_r : wih_f;
    const float* whh = dir ? whh_r : whh_f;
    const float* bb  = dir ? b_r  : b_f;

    __shared__ float sxc[BT1][64];
    __shared__ float sh[BT1][H1];
    __shared__ float szA[BT1][G1];
    __shared__ float szB[BT1][G1];

    for (int i = tid; i < BT1 * H1; i += 256) ((float*)sh)[i] = 0.f;

    ull wp0[16], wp1[16];
    {
        const ull* w0 = (const ull*)(whh + (2 * gp)     * H1 + 32 * half);
        const ull* w1 = (const ull*)(whh + (2 * gp + 1) * H1 + 32 * half);
#pragma unroll
        for (int j = 0; j < 16; j++) { wp0[j] = w0[j]; wp1[j] = w1[j]; }
    }
    const float wi0 = (half == 0) ? wih[2 * gp]     : 0.f;
    const float wi1 = (half == 0) ? wih[2 * gp + 1] : 0.f;
    const float bg0 = (half == 0) ? bb[2 * gp]      : 0.f;
    const float bg1 = (half == 0) ? bb[2 * gp + 1]  : 0.f;

    float c0 = 0.f, c1 = 0.f;
    const int cb = tid >> 6;
    const int ch = tid & 63;

    float* dst = half ? &szB[0][0] : &szA[0][0];

    __syncthreads();

    for (int tt = 0; tt < TT; ++tt) {
        const int t = dir ? (TT - 1 - tt) : tt;

        if ((tt & 63) == 0) {
            const int tbase = dir ? (448 - tt) : tt;
            for (int i = tid; i < BT1 * 64; i += 256) {
                int b = i >> 6, to = i & 63;
                sxc[b][to] = x[(size_t)(b0 + b) * TT + tbase + to];
            }
            __syncthreads();
        }
        const int ts = t & 63;

        // P1: cell(B, t-1) + FMA(A, t)
        if (tt > 0) {
            const int tp  = dir ? (TT - tt) : (tt - 1);
            const int cb2 = cb + 4;
            float zi = szA[cb2][ch]       + szB[cb2][ch];
            float zf = szA[cb2][64 + ch]  + szB[cb2][64 + ch];
            float zg = szA[cb2][128 + ch] + szB[cb2][128 + ch];
            float zo = szA[cb2][192 + ch] + szB[cb2][192 + ch];
            c1 = sigm(zf) * c1 + sigm(zi) * tanh_(zg);
            float hv = sigm(zo) * tanh_(c1);
            sh[cb2][ch] = hv;
            g_h1[((size_t)tp * BB + (b0 + cb2)) * 128 + dir * 64 + ch] = hv;
        }
        {
            ull a0[4], a1[4];
            if (half == 0) {
#pragma unroll
                for (int b = 0; b < 4; b++) {
                    float xv = sxc[b][ts];
                    a0[b] = pack2(fmaf(xv, wi0, bg0), 0.f);
                    a1[b] = pack2(fmaf(xv, wi1, bg1), 0.f);
                }
            } else {
#pragma unroll
                for (int b = 0; b < 4; b++) { a0[b] = 0ULL; a1[b] = 0ULL; }
            }
#pragma unroll
            for (int j = 0; j < 8; j++) {
#pragma unroll
                for (int b = 0; b < 4; b++) {
                    ulonglong2 hv = *(const ulonglong2*)&sh[b][32 * half + 4 * j];
                    ffma2(a0[b], hv.x, wp0[2 * j]);
                    ffma2(a0[b], hv.y, wp0[2 * j + 1]);
                    ffma2(a1[b], hv.x, wp1[2 * j]);
                    ffma2(a1[b], hv.y, wp1[2 * j + 1]);
                }
            }
#pragma unroll
            for (int b = 0; b < 4; b++)
                *(ull*)(dst + b * G1 + 2 * gp) = pack2(hadd2(a0[b]), hadd2(a1[b]));
        }
        __syncthreads();

        // P2: cell(A, t) + FMA(B, t)
        {
            float zi = szA[cb][ch]       + szB[cb][ch];
            float zf = szA[cb][64 + ch]  + szB[cb][64 + ch];
            float zg = szA[cb][128 + ch] + szB[cb][128 + ch];
            float zo = szA[cb][192 + ch] + szB[cb][192 + ch];
            c0 = sigm(zf) * c0 + sigm(zi) * tanh_(zg);
            float hv = sigm(zo) * tanh_(c0);
            sh[cb][ch] = hv;
            g_h1[((size_t)t * BB + (b0 + cb)) * 128 + dir * 64 + ch] = hv;
        }
        {
            ull a0[4], a1[4];
            if (half == 0) {
#pragma unroll
                for (int b = 0; b < 4; b++) {
                    float xv = sxc[b + 4][ts];
                    a0[b] = pack2(fmaf(xv, wi0, bg0), 0.f);
                    a1[b] = pack2(fmaf(xv, wi1, bg1), 0.f);
                }
            } else {
#pragma unroll
                for (int b = 0; b < 4; b++) { a0[b] = 0ULL; a1[b] = 0ULL; }
            }
#pragma unroll
            for (int j = 0; j < 8; j++) {
#pragma unroll
                for (int b = 0; b < 4; b++) {
                    ulonglong2 hv = *(const ulonglong2*)&sh[b + 4][32 * half + 4 * j];
                    ffma2(a0[b], hv.x, wp0[2 * j]);
                    ffma2(a0[b], hv.y, wp0[2 * j + 1]);
                    ffma2(a1[b], hv.x, wp1[2 * j]);
                    ffma2(a1[b], hv.y, wp1[2 * j + 1]);
                }
            }
#pragma unroll
            for (int b = 0; b < 4; b++)
                *(ull*)(dst + (b + 4) * G1 + 2 * gp) = pack2(hadd2(a0[b]), hadd2(a1[b]));
        }
        __syncthreads();
    }

    {
        const int tp  = dir ? 0 : (TT - 1);
        const int cb2 = cb + 4;
        float zi = szA[cb2][ch]       + szB[cb2][ch];
        float zf = szA[cb2][64 + ch]  + szB[cb2][64 + ch];
        float zg = szA[cb2][128 + ch] + szB[cb2][128 + ch];
        float zo = szA[cb2][192 + ch] + szB[cb2][192 + ch];
        c1 = sigm(zf) * c1 + sigm(zi) * tanh_(zg);
        float hv = sigm(zo) * tanh_(c1);
        g_h1[((size_t)tp * BB + (b0 + cb2)) * 128 + dir * 64 + ch] = hv;
    }
}

// ---------------------------------------------------------------------------
// Kernel 2: xi = h1 @ Wih2f^T + b2f via tf32 tensor cores.
// M = TT*BB, N = 128, K = 128.  grid = 4096, block = 256 (8 warps).
// Block tile 128m x 128n; warps 2m x 4n, warp tile m64 x n32.
// k16 slabs, double-buffered.  Smem pitch 20 -> fragment LDS conflict-free.
// ---------------------------------------------------------------------------
__global__ __launch_bounds__(256, 2)
void xi_gemm_tc(const float* __restrict__ W,     // wih2f [128][128] (n rows, k cols)
                const float* __restrict__ bias)  // b2f [128]
{
    const int tid    = threadIdx.x;
    const int wid    = tid >> 5;
    const int lane   = tid & 31;
    const int warp_m = wid >> 2;           // 0..1
    const int warp_n = wid & 3;            // 0..3
    const int m0w    = warp_m * 64;
    const int n0w    = warp_n * 32;
    const size_t mbase = (size_t)blockIdx.x * 128;

    __shared__ uint32_t As[2][128][20];    // [row m][k 0..15 + pad]
    __shared__ uint32_t Ws[2][128][20];    // [row n][k 0..15 + pad]

    const int gid = lane >> 2;             // group id (0..7)
    const int tig = lane & 3;              // thread in group (0..3)

    // C fragments [mt][nt][4], init with bias
    float c[4][4][4];
#pragma unroll
    for (int nt = 0; nt < 4; nt++) {
        int col = n0w + nt * 8 + 2 * tig;
        float bv0 = bias[col], bv1 = bias[col + 1];
#pragma unroll
        for (int mt = 0; mt < 4; mt++) {
            c[mt][nt][0] = bv0; c[mt][nt][1] = bv1;
            c[mt][nt][2] = bv0; c[mt][nt][3] = bv1;
        }
    }

    // staging roles: thread stages row srow, k-quads at skq, skq+4
    const int srow = tid & 127;
    const int skq  = (tid >> 7) * 8;       // 0 or 8

    // prologue: stage slab 0
    {
        float4 av0 = *(const float4*)(g_h1 + (mbase + srow) * 128 + skq);
        float4 av1 = *(const float4*)(g_h1 + (mbase + srow) * 128 + skq + 4);
        float4 wv0 = *(const float4*)(W + srow * 128 + skq);
        float4 wv1 = *(const float4*)(W + srow * 128 + skq + 4);
        uint4 a0 = make_uint4(to_tf32(av0.x), to_tf32(av0.y), to_tf32(av0.z), to_tf32(av0.w));
        uint4 a1 = make_uint4(to_tf32(av1.x), to_tf32(av1.y), to_tf32(av1.z), to_tf32(av1.w));
        uint4 w0 = make_uint4(to_tf32(wv0.x), to_tf32(wv0.y), to_tf32(wv0.z), to_tf32(wv0.w));
        uint4 w1 = make_uint4(to_tf32(wv1.x), to_tf32(wv1.y), to_tf32(wv1.z), to_tf32(wv1.w));
        *(uint4*)&As[0][srow][skq]     = a0;
        *(uint4*)&As[0][srow][skq + 4] = a1;
        *(uint4*)&Ws[0][srow][skq]     = w0;
        *(uint4*)&Ws[0][srow][skq + 4] = w1;
    }
    __syncthreads();

    for (int s = 0; s < 8; ++s) {                 // 8 slabs of k16
        const int cur = s & 1;

        // prefetch next slab into registers
        float4 av0, av1, wv0, wv1;
        const bool more = (s + 1 < 8);
        if (more) {
            const int ks = (s + 1) * 16;
            av0 = *(const float4*)(g_h1 + (mbase + srow) * 128 + ks + skq);
            av1 = *(const float4*)(g_h1 + (mbase + srow) * 128 + ks + skq + 4);
            wv0 = *(const float4*)(W + srow * 128 + ks + skq);
            wv1 = *(const float4*)(W + srow * 128 + ks + skq + 4);
        }

        // compute 2 k8 chunks of this slab
#pragma unroll
        for (int ck = 0; ck < 2; ck++) {
            const int kk = ck * 8;
            // a fragments for 4 m-tiles
            uint32_t a[4][4];
#pragma unroll
            for (int mt = 0; mt < 4; mt++) {
                int r = m0w + mt * 16 + gid;
                a[mt][0] = As[cur][r][kk + tig];
                a[mt][1] = As[cur][r + 8][kk + tig];
                a[mt][2] = As[cur][r][kk + tig + 4];
                a[mt][3] = As[cur][r + 8][kk + tig + 4];
            }
            // b fragments for 4 n-tiles
            uint32_t bfr[4][2];
#pragma unroll
            for (int nt = 0; nt < 4; nt++) {
                int n = n0w + nt * 8 + gid;
                bfr[nt][0] = Ws[cur][n][kk + tig];
                bfr[nt][1] = Ws[cur][n][kk + tig + 4];
            }
#pragma unroll
            for (int mt = 0; mt < 4; mt++)
#pragma unroll
                for (int nt = 0; nt < 4; nt++)
                    mma_tf32(c[mt][nt][0], c[mt][nt][1], c[mt][nt][2], c[mt][nt][3],
                             a[mt][0], a[mt][1], a[mt][2], a[mt][3],
                             bfr[nt][0], bfr[nt][1]);
        }

        // park prefetched slab
        if (more) {
            const int nxt = 1 - cur;
            uint4 a0 = make_uint4(to_tf32(av0.x), to_tf32(av0.y), to_tf32(av0.z), to_tf32(av0.w));
            uint4 a1 = make_uint4(to_tf32(av1.x), to_tf32(av1.y), to_tf32(av1.z), to_tf32(av1.w));
            uint4 w0 = make_uint4(to_tf32(wv0.x), to_tf32(wv0.y), to_tf32(wv0.z), to_tf32(wv0.w));
            uint4 w1 = make_uint4(to_tf32(wv1.x), to_tf32(wv1.y), to_tf32(wv1.z), to_tf32(wv1.w));
            *(uint4*)&As[nxt][srow][skq]     = a0;
            *(uint4*)&As[nxt][srow][skq + 4] = a1;
            *(uint4*)&Ws[nxt][srow][skq]     = w0;
            *(uint4*)&Ws[nxt][srow][skq + 4] = w1;
        }
        __syncthreads();
    }

    // write back
#pragma unroll
    for (int mt = 0; mt < 4; mt++) {
        const size_t r0 = mbase + m0w + mt * 16 + gid;
#pragma unroll
        for (int nt = 0; nt < 4; nt++) {
            const int col = n0w + nt * 8 + 2 * tig;
            *(float2*)(g_xi + r0 * 128 + col)       = make_float2(c[mt][nt][0], c[mt][nt][1]);
            *(float2*)(g_xi + (r0 + 8) * 128 + col) = make_float2(c[mt][nt][2], c[mt][nt][3]);
        }
    }
}

// ---------------------------------------------------------------------------
// Kernel 3: layer-2 recurrent scan (warp per batch, no block barriers in loop)
// + single reverse step + MLP head.  (unchanged)
// ---------------------------------------------------------------------------
__global__ __launch_bounds__(256, 1)
void lstm2_scan_kernel(const float* __restrict__ whh2f,
                       const float* __restrict__ wih2r, const float* __restrict__ b2r,
                       const float* __restrict__ w_fc1, const float* __restrict__ b_fc1,
                       const float* __restrict__ w_out, const float* __restrict__ b_out,
                       float* __restrict__ out)
{
    const int b0  = blockIdx.x * 8;
    const int tid = threadIdx.x;
    const int w   = tid >> 5;
    const int j   = tid & 31;
    const int bb  = b0 + w;

    __shared__ float shh[8][32];
    __shared__ float h1last[8][128];
    __shared__ float zrev[8][128];
    __shared__ float slast[8][64];
    __shared__ float sfc[8][64];

    ull wq[4][16];
#pragma unroll
    for (int q = 0; q < 4; q++) {
        const ull* wr = (const ull*)(whh2f + (q * 32 + j) * H2);
#pragma unroll
        for (int p = 0; p < 16; p++) wq[q][p] = wr[p];
    }

    shh[w][j] = 0.f;
    float c = 0.f, hmine = 0.f;

    const float* xibase = g_xi + (size_t)bb * 128 + j;
    float xin[4];
#pragma unroll
    for (int q = 0; q < 4; q++) xin[q] = xibase[q * 32];

    __syncwarp();

    for (int t = 0; t < TT; ++t) {
        float xnx[4] = {0.f, 0.f, 0.f, 0.f};
        if (t + 1 < TT) {
            const float* p = xibase + (size_t)(t + 1) * BB * 128;
#pragma unroll
            for (int q = 0; q < 4; q++) xnx[q] = p[q * 32];
        }

        ull acc[4];
#pragma unroll
        for (int q = 0; q < 4; q++) acc[q] = pack2(xin[q], 0.f);

#pragma unroll
        for (int p = 0; p < 16; p++) {
            ull hv = *(const ull*)&shh[w][2 * p];
#pragma unroll
            for (int q = 0; q < 4; q++) ffma2(acc[q], hv, wq[q][p]);
        }
        float zi = hadd2(acc[0]);
        float zf = hadd2(acc[1]);
        float zg = hadd2(acc[2]);
        float zo = hadd2(acc[3]);
        c = sigm(zf) * c + sigm(zi) * tanh_(zg);
        hmine = sigm(zo) * tanh_(c);

        __syncwarp();
        shh[w][j] = hmine;
        __syncwarp();

#pragma unroll
        for (int q = 0; q < 4; q++) xin[q] = xnx[q];
    }

    __syncthreads();

    {
        int idx = tid * 4;
        int b = idx >> 7, k = idx & 127;
        *(float4*)&h1last[b][k] =
            *(const float4*)(g_h1 + ((size_t)(TT - 1) * BB + b0 + b) * 128 + k);
    }
    __syncthreads();

    {
        const int g2 = tid & 127;
        const int hf = tid >> 7;
        const float brv = b2r[g2];
        float a[4] = {brv, brv, brv, brv};
        const float* wr = wih2r + g2 * G2;
        for (int k = 0; k < G2; k++) {
            float wv = __ldg(wr + k);
#pragma unroll
            for (int b = 0; b < 4; b++)
                a[b] = fmaf(h1last[hf * 4 + b][k], wv, a[b]);
        }
#pragma unroll
        for (int b = 0; b < 4; b++) zrev[hf * 4 + b][g2] = a[b];
    }
    __syncthreads();
    {
        const int b = tid >> 5, jj = tid & 31;
        float zi = zrev[b][jj];
        float zg = zrev[b][64 + jj], zo = zrev[b][96 + jj];
        float cr = sigm(zi) * tanh_(zg);
        float hr = sigm(zo) * tanh_(cr);
        slast[b][jj]      = shh[b][jj];
        slast[b][32 + jj] = hr;
    }
    __syncthreads();

#pragma unroll
    for (int rep = 0; rep < 2; rep++) {
        int item = tid + rep * 256;
        int b = item >> 6, o = item & 63;
        float a = b_fc1[o];
        const float* wf = w_fc1 + o * 64;
        for (int k = 0; k < 64; k++) a = fmaf(slast[b][k], __ldg(wf + k), a);
        sfc[b][o] = fmaxf(a, 0.f);
    }
    __syncthreads();

    if (tid < 8) {
        float a = b_out[0];
        for (int k = 0; k < 64; k++) a = fmaf(sfc[tid][k], __ldg(w_out + k), a);
        out[b0 + tid] = sigm(a);
    }
}

// ---------------------------------------------------------------------------
extern "C" void kernel_launch(void* const* d_in, const int* in_sizes, int n_in,
                              void* d_out, int out_size)
{
    (void)in_sizes; (void)n_in; (void)out_size;
    const float* x     = (const float*)d_in[0];
    const float* wih1f = (const float*)d_in[1];
    const float* whh1f = (const float*)d_in[2];
    const float* b1f   = (const float*)d_in[3];
    const float* wih1r = (const float*)d_in[4];
    const float* whh1r = (const float*)d_in[5];
    const float* b1r   = (const float*)d_in[6];
    const float* wih2f = (const float*)d_in[7];
    const float* whh2f = (const float*)d_in[8];
    const float* b2f   = (const float*)d_in[9];
    const float* wih2r = (const float*)d_in[10];
    const float* b2r   = (const float*)d_in[12];
    const float* w_fc1 = (const float*)d_in[13];
    const float* b_fc1 = (const float*)d_in[14];
    const float* w_out = (const float*)d_in[15];
    const float* b_out = (const float*)d_in[16];
    float* out = (float*)d_out;

    lstm1_kernel<<<dim3(BB / BT1, 2), 256>>>(x, wih1f, whh1f, b1f, wih1r, whh1r, b1r);
    xi_gemm_tc<<<(TT * BB) / 128, 256>>>(wih2f, b2f);
    lstm2_scan_kernel<<<BB / 8, 256>>>(whh2f, wih2r, b2r,
                                       w_fc1, b_fc1, w_out, b_out, out);
}

// round 11
// speedup vs baseline: 2.7668x; 1.7299x over previous
#include <cuda_runtime.h>
#include <cstdint>

#define TT   512
#define BB   1024
#define H1   64
#define G1   256     // 4*H1
#define H2   32
#define G2   128     // 4*H2

typedef unsigned long long ull;

// scratch: h1[t][b][j], j in [0,128): fwd half [0,64), rev half [64,128)
__device__ float g_h1[(size_t)TT * BB * 128];
// precomputed layer-2 input projection + bias: xi[t][b][g], g in [0,128)
__device__ float g_xi[(size_t)TT * BB * 128];

// ---- fast activations -----------------------------------------------------
__device__ __forceinline__ float tanh_(float x) {
    float y;
    asm("tanh.approx.f32 %0, %1;" : "=f"(y) : "f"(x));
    return y;
}
__device__ __forceinline__ float sigm(float x) {
    return fmaf(tanh_(x * 0.5f), 0.5f, 0.5f);
}

// ---- packed fp32x2 fma ----------------------------------------------------
__device__ __forceinline__ void ffma2(ull& acc, ull a, ull b) {
    asm("fma.rn.f32x2 %0, %1, %2, %0;" : "+l"(acc) : "l"(a), "l"(b));
}
__device__ __forceinline__ ull pack2(float lo, float hi) {
    ull r;
    asm("mov.b64 %0, {%1, %2};" : "=l"(r) : "f"(lo), "f"(hi));
    return r;
}
__device__ __forceinline__ float hadd2(ull v) {
    float lo, hi;
    asm("mov.b64 {%0, %1}, %2;" : "=f"(lo), "=f"(hi) : "l"(v));
    return lo + hi;
}

// ---- tf32 helpers -----------------------------------------------------------
__device__ __forceinline__ uint32_t to_tf32(float x) {
    uint32_t r;
    asm("cvt.rna.tf32.f32 %0, %1;" : "=r"(r) : "f"(x));
    return r;
}
__device__ __forceinline__ void mma_tf32(float& c0, float& c1, float& c2, float& c3,
                                         uint32_t a0, uint32_t a1, uint32_t a2, uint32_t a3,
                                         uint32_t b0, uint32_t b1) {
    asm("mma.sync.aligned.m16n8k8.row.col.f32.tf32.tf32.f32 "
        "{%0,%1,%2,%3}, {%4,%5,%6,%7}, {%8,%9}, {%0,%1,%2,%3};"
        : "+f"(c0), "+f"(c1), "+f"(c2), "+f"(c3)
        : "r"(a0), "r"(a1), "r"(a2), "r"(a3), "r"(b0), "r"(b1));
}

// ---------------------------------------------------------------------------
// Kernel 1: bidirectional layer-1 LSTM via tf32 tensor cores.
// grid = (64, 2), block = 256 (8 warps), 16 batches/block.
// Per step: z[16,256] = h[16,64] @ Whh^T  via mma.m16n8k8.
// Warp w owns gate cols {64q + 8w .. +7}, q in {i,f,g,o}; Whh frags in regs.
// C-fragment layout => thread holds all 4 gates for its 2 batches x 2 cells;
// cell state lives in registers; no gate-partial smem traffic.
// ---------------------------------------------------------------------------
__global__ __launch_bounds__(256, 1)
void lstm1_tc(const float* __restrict__ x,
              const float* __restrict__ wih_f, const float* __restrict__ whh_f,
              const float* __restrict__ b_f,
              const float* __restrict__ wih_r, const float* __restrict__ whh_r,
              const float* __restrict__ b_r)
{
    const int dir  = blockIdx.y;
    const int b0   = blockIdx.x * 16;
    const int tid  = threadIdx.x;
    const int w    = tid >> 5;
    const int lane = tid & 31;
    const int gid  = lane >> 2;          // 0..7 (batch row)
    const int tig  = lane & 3;

    const float* wih = dir ? wih_r : wih_f;
    const float* whh = dir ? whh_r : whh_f;
    const float* bb  = dir ? b_r  : b_f;

    __shared__ float    sxc[16][64];     // 4 KB x chunk
    __shared__ uint32_t hs[16][68];      // h in tf32, padded

    // Whh B-fragments, resident in registers: [gate q][k-chunk][2]
    uint32_t bf[4][8][2];
#pragma unroll
    for (int q = 0; q < 4; q++) {
        const int row = 64 * q + 8 * w + gid;
#pragma unroll
        for (int kc = 0; kc < 8; kc++) {
            bf[q][kc][0] = to_tf32(whh[row * 64 + 8 * kc + tig]);
            bf[q][kc][1] = to_tf32(whh[row * 64 + 8 * kc + tig + 4]);
        }
    }
    const int cell0 = 8 * w + 2 * tig;   // this thread's cells: cell0, cell0+1
    float wi[4][2], bs4[4][2];
#pragma unroll
    for (int q = 0; q < 4; q++) {
        wi[q][0]  = wih[64 * q + cell0];
        wi[q][1]  = wih[64 * q + cell0 + 1];
        bs4[q][0] = bb[64 * q + cell0];
        bs4[q][1] = bb[64 * q + cell0 + 1];
    }

    // zero h (tf32 of 0 is 0)
    for (int i = tid; i < 16 * 68; i += 256) ((uint32_t*)hs)[i] = 0u;

    // register-resident cell states: j = {(gid,cell0),(gid,cell0+1),(gid+8,cell0),(gid+8,cell0+1)}
    float cc[4] = {0.f, 0.f, 0.f, 0.f};

    __syncthreads();

    for (int tt = 0; tt < TT; ++tt) {
        const int t = dir ? (TT - 1 - tt) : tt;

        if ((tt & 63) == 0) {
            const int tbase = dir ? (448 - tt) : tt;
            for (int i = tid; i < 16 * 64; i += 256) {
                int b = i >> 6, to = i & 63;
                sxc[b][to] = x[(size_t)(b0 + b) * TT + tbase + to];
            }
            __syncthreads();
        }
        const int ts = t & 63;

        // init z with input projection + bias
        const float xv0 = sxc[gid][ts];
        const float xv1 = sxc[gid + 8][ts];
        float c[4][4];
#pragma unroll
        for (int q = 0; q < 4; q++) {
            c[q][0] = fmaf(xv0, wi[q][0], bs4[q][0]);
            c[q][1] = fmaf(xv0, wi[q][1], bs4[q][1]);
            c[q][2] = fmaf(xv1, wi[q][0], bs4[q][0]);
            c[q][3] = fmaf(xv1, wi[q][1], bs4[q][1]);
        }

        // recurrent matvec: 8 k-chunks x 4 gate n-tiles
#pragma unroll
        for (int kc = 0; kc < 8; kc++) {
            uint32_t a0 = hs[gid][8 * kc + tig];
            uint32_t a1 = hs[gid + 8][8 * kc + tig];
            uint32_t a2 = hs[gid][8 * kc + tig + 4];
            uint32_t a3 = hs[gid + 8][8 * kc + tig + 4];
#pragma unroll
            for (int q = 0; q < 4; q++)
                mma_tf32(c[q][0], c[q][1], c[q][2], c[q][3],
                         a0, a1, a2, a3, bf[q][kc][0], bf[q][kc][1]);
        }

        // cell update, fully register-resident
        float h[4];
#pragma unroll
        for (int j = 0; j < 4; j++) {
            float zi = c[0][j], zf = c[1][j], zg = c[2][j], zo = c[3][j];
            cc[j] = sigm(zf) * cc[j] + sigm(zi) * tanh_(zg);
            h[j]  = sigm(zo) * tanh_(cc[j]);
        }

        __syncthreads();   // all warps' A-fragment reads of old h complete

        hs[gid][cell0]     = to_tf32(h[0]);
        hs[gid][cell0 + 1] = to_tf32(h[1]);
        hs[gid + 8][cell0]     = to_tf32(h[2]);
        hs[gid + 8][cell0 + 1] = to_tf32(h[3]);

        *(float2*)&g_h1[((size_t)t * BB + b0 + gid) * 128 + dir * 64 + cell0] =
            make_float2(h[0], h[1]);
        *(float2*)&g_h1[((size_t)t * BB + b0 + gid + 8) * 128 + dir * 64 + cell0] =
            make_float2(h[2], h[3]);

        __syncthreads();   // new h visible before next step's reads
    }
}

// ---------------------------------------------------------------------------
// Kernel 2: xi = h1 @ Wih2f^T + b2f via tf32 tensor cores.  (unchanged)
// ---------------------------------------------------------------------------
__global__ __launch_bounds__(256, 2)
void xi_gemm_tc(const float* __restrict__ W,     // wih2f [128][128]
                const float* __restrict__ bias)  // b2f [128]
{
    const int tid    = threadIdx.x;
    const int wid    = tid >> 5;
    const int lane   = tid & 31;
    const int warp_m = wid >> 2;
    const int warp_n = wid & 3;
    const int m0w    = warp_m * 64;
    const int n0w    = warp_n * 32;
    const size_t mbase = (size_t)blockIdx.x * 128;

    __shared__ uint32_t As[2][128][20];
    __shared__ uint32_t Ws[2][128][20];

    const int gid = lane >> 2;
    const int tig = lane & 3;

    float c[4][4][4];
#pragma unroll
    for (int nt = 0; nt < 4; nt++) {
        int col = n0w + nt * 8 + 2 * tig;
        float bv0 = bias[col], bv1 = bias[col + 1];
#pragma unroll
        for (int mt = 0; mt < 4; mt++) {
            c[mt][nt][0] = bv0; c[mt][nt][1] = bv1;
            c[mt][nt][2] = bv0; c[mt][nt][3] = bv1;
        }
    }

    const int srow = tid & 127;
    const int skq  = (tid >> 7) * 8;

    {
        float4 av0 = *(const float4*)(g_h1 + (mbase + srow) * 128 + skq);
        float4 av1 = *(const float4*)(g_h1 + (mbase + srow) * 128 + skq + 4);
        float4 wv0 = *(const float4*)(W + srow * 128 + skq);
        float4 wv1 = *(const float4*)(W + srow * 128 + skq + 4);
        *(uint4*)&As[0][srow][skq]     = make_uint4(to_tf32(av0.x), to_tf32(av0.y), to_tf32(av0.z), to_tf32(av0.w));
        *(uint4*)&As[0][srow][skq + 4] = make_uint4(to_tf32(av1.x), to_tf32(av1.y), to_tf32(av1.z), to_tf32(av1.w));
        *(uint4*)&Ws[0][srow][skq]     = make_uint4(to_tf32(wv0.x), to_tf32(wv0.y), to_tf32(wv0.z), to_tf32(wv0.w));
        *(uint4*)&Ws[0][srow][skq + 4] = make_uint4(to_tf32(wv1.x), to_tf32(wv1.y), to_tf32(wv1.z), to_tf32(wv1.w));
    }
    __syncthreads();

    for (int s = 0; s < 8; ++s) {
        const int cur = s & 1;

        float4 av0, av1, wv0, wv1;
        const bool more = (s + 1 < 8);
        if (more) {
            const int ks = (s + 1) * 16;
            av0 = *(const float4*)(g_h1 + (mbase + srow) * 128 + ks + skq);
            av1 = *(const float4*)(g_h1 + (mbase + srow) * 128 + ks + skq + 4);
            wv0 = *(const float4*)(W + srow * 128 + ks + skq);
            wv1 = *(const float4*)(W + srow * 128 + ks + skq + 4);
        }

#pragma unroll
        for (int ck = 0; ck < 2; ck++) {
            const int kk = ck * 8;
            uint32_t a[4][4];
#pragma unroll
            for (int mt = 0; mt < 4; mt++) {
                int r = m0w + mt * 16 + gid;
                a[mt][0] = As[cur][r][kk + tig];
                a[mt][1] = As[cur][r + 8][kk + tig];
                a[mt][2] = As[cur][r][kk + tig + 4];
                a[mt][3] = As[cur][r + 8][kk + tig + 4];
            }
            uint32_t bfr[4][2];
#pragma unroll
            for (int nt = 0; nt < 4; nt++) {
                int n = n0w + nt * 8 + gid;
                bfr[nt][0] = Ws[cur][n][kk + tig];
                bfr[nt][1] = Ws[cur][n][kk + tig + 4];
            }
#pragma unroll
            for (int mt = 0; mt < 4; mt++)
#pragma unroll
                for (int nt = 0; nt < 4; nt++)
                    mma_tf32(c[mt][nt][0], c[mt][nt][1], c[mt][nt][2], c[mt][nt][3],
                             a[mt][0], a[mt][1], a[mt][2], a[mt][3],
                             bfr[nt][0], bfr[nt][1]);
        }

        if (more) {
            const int nxt = 1 - cur;
            *(uint4*)&As[nxt][srow][skq]     = make_uint4(to_tf32(av0.x), to_tf32(av0.y), to_tf32(av0.z), to_tf32(av0.w));
            *(uint4*)&As[nxt][srow][skq + 4] = make_uint4(to_tf32(av1.x), to_tf32(av1.y), to_tf32(av1.z), to_tf32(av1.w));
            *(uint4*)&Ws[nxt][srow][skq]     = make_uint4(to_tf32(wv0.x), to_tf32(wv0.y), to_tf32(wv0.z), to_tf32(wv0.w));
            *(uint4*)&Ws[nxt][srow][skq + 4] = make_uint4(to_tf32(wv1.x), to_tf32(wv1.y), to_tf32(wv1.z), to_tf32(wv1.w));
        }
        __syncthreads();
    }

#pragma unroll
    for (int mt = 0; mt < 4; mt++) {
        const size_t r0 = mbase + m0w + mt * 16 + gid;
#pragma unroll
        for (int nt = 0; nt < 4; nt++) {
            const int col = n0w + nt * 8 + 2 * tig;
            *(float2*)(g_xi + r0 * 128 + col)       = make_float2(c[mt][nt][0], c[mt][nt][1]);
            *(float2*)(g_xi + (r0 + 8) * 128 + col) = make_float2(c[mt][nt][2], c[mt][nt][3]);
        }
    }
}

// ---------------------------------------------------------------------------
// Kernel 3: layer-2 recurrent scan + reverse step + MLP head.  (unchanged)
// ---------------------------------------------------------------------------
__global__ __launch_bounds__(256, 1)
void lstm2_scan_kernel(const float* __restrict__ whh2f,
                       const float* __restrict__ wih2r, const float* __restrict__ b2r,
                       const float* __restrict__ w_fc1, const float* __restrict__ b_fc1,
                       const float* __restrict__ w_out, const float* __restrict__ b_out,
                       float* __restrict__ out)
{
    const int b0  = blockIdx.x * 8;
    const int tid = threadIdx.x;
    const int w   = tid >> 5;
    const int j   = tid & 31;
    const int bb  = b0 + w;

    __shared__ float shh[8][32];
    __shared__ float h1last[8][128];
    __shared__ float zrev[8][128];
    __shared__ float slast[8][64];
    __shared__ float sfc[8][64];

    ull wq[4][16];
#pragma unroll
    for (int q = 0; q < 4; q++) {
        const ull* wr = (const ull*)(whh2f + (q * 32 + j) * H2);
#pragma unroll
        for (int p = 0; p < 16; p++) wq[q][p] = wr[p];
    }

    shh[w][j] = 0.f;
    float c = 0.f, hmine = 0.f;

    const float* xibase = g_xi + (size_t)bb * 128 + j;
    float xin[4];
#pragma unroll
    for (int q = 0; q < 4; q++) xin[q] = xibase[q * 32];

    __syncwarp();

    for (int t = 0; t < TT; ++t) {
        float xnx[4] = {0.f, 0.f, 0.f, 0.f};
        if (t + 1 < TT) {
            const float* p = xibase + (size_t)(t + 1) * BB * 128;
#pragma unroll
            for (int q = 0; q < 4; q++) xnx[q] = p[q * 32];
        }

        ull acc[4];
#pragma unroll
        for (int q = 0; q < 4; q++) acc[q] = pack2(xin[q], 0.f);

#pragma unroll
        for (int p = 0; p < 16; p++) {
            ull hv = *(const ull*)&shh[w][2 * p];
#pragma unroll
            for (int q = 0; q < 4; q++) ffma2(acc[q], hv, wq[q][p]);
        }
        float zi = hadd2(acc[0]);
        float zf = hadd2(acc[1]);
        float zg = hadd2(acc[2]);
        float zo = hadd2(acc[3]);
        c = sigm(zf) * c + sigm(zi) * tanh_(zg);
        hmine = sigm(zo) * tanh_(c);

        __syncwarp();
        shh[w][j] = hmine;
        __syncwarp();

#pragma unroll
        for (int q = 0; q < 4; q++) xin[q] = xnx[q];
    }

    __syncthreads();

    {
        int idx = tid * 4;
        int b = idx >> 7, k = idx & 127;
        *(float4*)&h1last[b][k] =
            *(const float4*)(g_h1 + ((size_t)(TT - 1) * BB + b0 + b) * 128 + k);
    }
    __syncthreads();

    {
        const int g2 = tid & 127;
        const int hf = tid >> 7;
        const float brv = b2r[g2];
        float a[4] = {brv, brv, brv, brv};
        const float* wr = wih2r + g2 * G2;
        for (int k = 0; k < G2; k++) {
            float wv = __ldg(wr + k);
#pragma unroll
            for (int b = 0; b < 4; b++)
                a[b] = fmaf(h1last[hf * 4 + b][k], wv, a[b]);
        }
#pragma unroll
        for (int b = 0; b < 4; b++) zrev[hf * 4 + b][g2] = a[b];
    }
    __syncthreads();
    {
        const int b = tid >> 5, jj = tid & 31;
        float zi = zrev[b][jj];
        float zg = zrev[b][64 + jj], zo = zrev[b][96 + jj];
        float cr = sigm(zi) * tanh_(zg);
        float hr = sigm(zo) * tanh_(cr);
        slast[b][jj]      = shh[b][jj];
        slast[b][32 + jj] = hr;
    }
    __syncthreads();

#pragma unroll
    for (int rep = 0; rep < 2; rep++) {
        int item = tid + rep * 256;
        int b = item >> 6, o = item & 63;
        float a = b_fc1[o];
        const float* wf = w_fc1 + o * 64;
        for (int k = 0; k < 64; k++) a = fmaf(slast[b][k], __ldg(wf + k), a);
        sfc[b][o] = fmaxf(a, 0.f);
    }
    __syncthreads();

    if (tid < 8) {
        float a = b_out[0];
        for (int k = 0; k < 64; k++) a = fmaf(sfc[tid][k], __ldg(w_out + k), a);
        out[b0 + tid] = sigm(a);
    }
}

// ---------------------------------------------------------------------------
extern "C" void kernel_launch(void* const* d_in, const int* in_sizes, int n_in,
                              void* d_out, int out_size)
{
    (void)in_sizes; (void)n_in; (void)out_size;
    const float* x     = (const float*)d_in[0];
    const float* wih1f = (const float*)d_in[1];
    const float* whh1f = (const float*)d_in[2];
    const float* b1f   = (const float*)d_in[3];
    const float* wih1r = (const float*)d_in[4];
    const float* whh1r = (const float*)d_in[5];
    const float* b1r   = (const float*)d_in[6];
    const float* wih2f = (const float*)d_in[7];
    const float* whh2f = (const float*)d_in[8];
    const float* b2f   = (const float*)d_in[9];
    const float* wih2r = (const float*)d_in[10];
    const float* b2r   = (const float*)d_in[12];
    const float* w_fc1 = (const float*)d_in[13];
    const float* b_fc1 = (const float*)d_in[14];
    const float* w_out = (const float*)d_in[15];
    const float* b_out = (const float*)d_in[16];
    float* out = (float*)d_out;

    lstm1_tc<<<dim3(BB / 16, 2), 256>>>(x, wih1f, whh1f, b1f, wih1r, whh1r, b1r);
    xi_gemm_tc<<<(TT * BB) / 128, 256>>>(wih2f, b2f);
    lstm2_scan_kernel<<<BB / 8, 256>>>(whh2f, wih2r, b2r,
                                       w_fc1, b_fc1, w_out, b_out, out);
}

// round 13
// speedup vs baseline: 2.8080x; 1.0149x over previous
#include <cuda_runtime.h>
#include <cstdint>

#define TT   512
#define BB   1024
#define H1   64
#define H2   32
#define G2   128     // 4*H2

typedef unsigned long long ull;

// scratch: h1[t][b][j] (values tf32-rounded), j in [0,128): fwd [0,64), rev [64,128)
__device__ float g_h1[(size_t)TT * BB * 128];
// precomputed layer-2 input projection + bias: xi[t][b][g]
__device__ float g_xi[(size_t)TT * BB * 128];

// ---- fast activations -----------------------------------------------------
__device__ __forceinline__ float tanh_(float x) {
    float y;
    asm("tanh.approx.f32 %0, %1;" : "=f"(y) : "f"(x));
    return y;
}
__device__ __forceinline__ float sigm(float x) {
    return fmaf(tanh_(x * 0.5f), 0.5f, 0.5f);
}

// ---- packed fp32x2 fma ----------------------------------------------------
__device__ __forceinline__ void ffma2(ull& acc, ull a, ull b) {
    asm("fma.rn.f32x2 %0, %1, %2, %0;" : "+l"(acc) : "l"(a), "l"(b));
}
__device__ __forceinline__ ull pack2(float lo, float hi) {
    ull r;
    asm("mov.b64 %0, {%1, %2};" : "=l"(r) : "f"(lo), "f"(hi));
    return r;
}
__device__ __forceinline__ float hadd2(ull v) {
    float lo, hi;
    asm("mov.b64 {%0, %1}, %2;" : "=f"(lo), "=f"(hi) : "l"(v));
    return lo + hi;
}

// ---- tf32 / mma helpers -----------------------------------------------------
__device__ __forceinline__ uint32_t to_tf32(float x) {
    uint32_t r;
    asm("cvt.rna.tf32.f32 %0, %1;" : "=r"(r) : "f"(x));
    return r;
}
__device__ __forceinline__ void mma_tf32(float& c0, float& c1, float& c2, float& c3,
                                         uint32_t a0, uint32_t a1, uint32_t a2, uint32_t a3,
                                         uint32_t b0, uint32_t b1) {
    asm("mma.sync.aligned.m16n8k8.row.col.f32.tf32.tf32.f32 "
        "{%0,%1,%2,%3}, {%4,%5,%6,%7}, {%8,%9}, {%0,%1,%2,%3};"
        : "+f"(c0), "+f"(c1), "+f"(c2), "+f"(c3)
        : "r"(a0), "r"(a1), "r"(a2), "r"(a3), "r"(b0), "r"(b1));
}

// ---- cp.async helpers -------------------------------------------------------
__device__ __forceinline__ uint32_t smem_u32(const void* p) {
    return (uint32_t)__cvta_generic_to_shared(p);
}
#define CP_ASYNC16(dst, src) \
    asm volatile("cp.async.ca.shared.global [%0], [%1], 16;" :: "r"(dst), "l"(src))
#define CP_COMMIT() asm volatile("cp.async.commit_group;")
#define CP_WAIT(n)  asm volatile("cp.async.wait_group %0;" :: "n"(n))

// ---------------------------------------------------------------------------
// Kernel 1: bidirectional layer-1 LSTM via tf32 tensor cores.
// grid = (64, 2), block = 256 (8 warps), 16 batches/block.
// Double-buffered h => ONE __syncthreads per step.
// h1 is stored tf32-rounded so the downstream GEMM needs no conversion.
// ---------------------------------------------------------------------------
__global__ __launch_bounds__(256, 1)
void lstm1_tc(const float* __restrict__ x,
              const float* __restrict__ wih_f, const float* __restrict__ whh_f,
              const float* __restrict__ b_f,
              const float* __restrict__ wih_r, const float* __restrict__ whh_r,
              const float* __restrict__ b_r)
{
    const int dir  = blockIdx.y;
    const int b0   = blockIdx.x * 16;
    const int tid  = threadIdx.x;
    const int w    = tid >> 5;
    const int lane = tid & 31;
    const int gid  = lane >> 2;          // 0..7
    const int tig  = lane & 3;

    const float* wih = dir ? wih_r : wih_f;
    const float* whh = dir ? whh_r : whh_f;
    const float* bb  = dir ? b_r  : b_f;

    __shared__ float    sxc[16][64];     // 4 KB x chunk
    __shared__ uint32_t hs[2][16][68];   // double-buffered tf32 h

    // Whh B-fragments in registers: [gate q][k-chunk][2]
    uint32_t bf[4][8][2];
#pragma unroll
    for (int q = 0; q < 4; q++) {
        const int row = 64 * q + 8 * w + gid;
#pragma unroll
        for (int kc = 0; kc < 8; kc++) {
            bf[q][kc][0] = to_tf32(whh[row * 64 + 8 * kc + tig]);
            bf[q][kc][1] = to_tf32(whh[row * 64 + 8 * kc + tig + 4]);
        }
    }
    const int cell0 = 8 * w + 2 * tig;
    float wi[4][2], bs4[4][2];
#pragma unroll
    for (int q = 0; q < 4; q++) {
        wi[q][0]  = wih[64 * q + cell0];
        wi[q][1]  = wih[64 * q + cell0 + 1];
        bs4[q][0] = bb[64 * q + cell0];
        bs4[q][1] = bb[64 * q + cell0 + 1];
    }

    for (int i = tid; i < 16 * 68; i += 256) ((uint32_t*)hs[0])[i] = 0u;

    float cc[4] = {0.f, 0.f, 0.f, 0.f};

    __syncthreads();

    for (int tt = 0; tt < TT; ++tt) {
        const int t   = dir ? (TT - 1 - tt) : tt;
        const int cur = tt & 1;
        const int nxt = 1 - cur;

        if ((tt & 63) == 0) {
            const int tbase = dir ? (448 - tt) : tt;
            for (int i = tid; i < 16 * 64; i += 256) {
                int b = i >> 6, to = i & 63;
                sxc[b][to] = x[(size_t)(b0 + b) * TT + tbase + to];
            }
            __syncthreads();
        }
        const int ts = t & 63;

        const float xv0 = sxc[gid][ts];
        const float xv1 = sxc[gid + 8][ts];
        float c[4][4];
#pragma unroll
        for (int q = 0; q < 4; q++) {
            c[q][0] = fmaf(xv0, wi[q][0], bs4[q][0]);
            c[q][1] = fmaf(xv0, wi[q][1], bs4[q][1]);
            c[q][2] = fmaf(xv1, wi[q][0], bs4[q][0]);
            c[q][3] = fmaf(xv1, wi[q][1], bs4[q][1]);
        }

#pragma unroll
        for (int kc = 0; kc < 8; kc++) {
            uint32_t a0 = hs[cur][gid][8 * kc + tig];
            uint32_t a1 = hs[cur][gid + 8][8 * kc + tig];
            uint32_t a2 = hs[cur][gid][8 * kc + tig + 4];
            uint32_t a3 = hs[cur][gid + 8][8 * kc + tig + 4];
#pragma unroll
            for (int q = 0; q < 4; q++)
                mma_tf32(c[q][0], c[q][1], c[q][2], c[q][3],
                         a0, a1, a2, a3, bf[q][kc][0], bf[q][kc][1]);
        }

        // cell update, register-resident; produce tf32-rounded h
        uint32_t ht[4];
#pragma unroll
        for (int j = 0; j < 4; j++) {
            float zi = c[0][j], zf = c[1][j], zg = c[2][j], zo = c[3][j];
            cc[j] = sigm(zf) * cc[j] + sigm(zi) * tanh_(zg);
            ht[j] = to_tf32(sigm(zo) * tanh_(cc[j]));
        }

        hs[nxt][gid][cell0]         = ht[0];
        hs[nxt][gid][cell0 + 1]     = ht[1];
        hs[nxt][gid + 8][cell0]     = ht[2];
        hs[nxt][gid + 8][cell0 + 1] = ht[3];

        *(float2*)&g_h1[((size_t)t * BB + b0 + gid) * 128 + dir * 64 + cell0] =
            make_float2(__uint_as_float(ht[0]), __uint_as_float(ht[1]));
        *(float2*)&g_h1[((size_t)t * BB + b0 + gid + 8) * 128 + dir * 64 + cell0] =
            make_float2(__uint_as_float(ht[2]), __uint_as_float(ht[3]));

        __syncthreads();   // single barrier per step
    }
}

// ---------------------------------------------------------------------------
// Kernel 2: xi = h1 @ Wih2f^T + b2f via tf32 tensor cores, 4-stage cp.async.
// Staging buffers in DYNAMIC shared memory (80 KB > 48 KB static cap).
// grid = 4096, block = 256 (8 warps); block tile 128m x 128n; k16 slabs.
// ---------------------------------------------------------------------------
#define NSTG 4
#define XI_SMEM_BYTES (2 * NSTG * 128 * 20 * 4)   // 81920

__global__ __launch_bounds__(256)
void xi_gemm_tc(const float* __restrict__ W,     // wih2f [128][128]
                const float* __restrict__ bias)  // b2f [128]
{
    extern __shared__ float dynsm[];
    float (*As)[128][20] = reinterpret_cast<float(*)[128][20]>(dynsm);
    float (*Ws)[128][20] = reinterpret_cast<float(*)[128][20]>(dynsm + NSTG * 128 * 20);

    const int tid    = threadIdx.x;
    const int wid    = tid >> 5;
    const int lane   = tid & 31;
    const int warp_m = wid >> 2;
    const int warp_n = wid & 3;
    const int m0w    = warp_m * 64;
    const int n0w    = warp_n * 32;
    const size_t mbase = (size_t)blockIdx.x * 128;

    const int gid = lane >> 2;
    const int tig = lane & 3;

    float c[4][4][4];
#pragma unroll
    for (int nt = 0; nt < 4; nt++) {
        int col = n0w + nt * 8 + 2 * tig;
        float bv0 = bias[col], bv1 = bias[col + 1];
#pragma unroll
        for (int mt = 0; mt < 4; mt++) {
            c[mt][nt][0] = bv0; c[mt][nt][1] = bv1;
            c[mt][nt][2] = bv0; c[mt][nt][3] = bv1;
        }
    }

    const int srow = tid & 127;
    const int skq  = (tid >> 7) * 8;        // 0 or 8
    const float* Aptr = g_h1 + (mbase + srow) * 128;
    const float* Wptr = W + srow * 128;

    // prologue: issue slabs 0..2 (one commit group each)
#pragma unroll
    for (int p = 0; p < 3; p++) {
        const int ks = p * 16;
        CP_ASYNC16(smem_u32(&As[p][srow][skq]),     Aptr + ks + skq);
        CP_ASYNC16(smem_u32(&As[p][srow][skq + 4]), Aptr + ks + skq + 4);
        CP_ASYNC16(smem_u32(&Ws[p][srow][skq]),     Wptr + ks + skq);
        CP_ASYNC16(smem_u32(&Ws[p][srow][skq + 4]), Wptr + ks + skq + 4);
        CP_COMMIT();
    }

    for (int s = 0; s < 8; ++s) {
        const int cur = s & (NSTG - 1);

        CP_WAIT(2);          // slab s complete (<=2 groups still pending)
        __syncthreads();     // visibility; all threads done with slab s-1's buffer

        // issue slab s+3 into buffer (s+3)%4 (consumed at iter s-1; safe post-sync)
        if (s + 3 < 8) {
            const int p  = (s + 3) & (NSTG - 1);
            const int ks = (s + 3) * 16;
            CP_ASYNC16(smem_u32(&As[p][srow][skq]),     Aptr + ks + skq);
            CP_ASYNC16(smem_u32(&As[p][srow][skq + 4]), Aptr + ks + skq + 4);
            CP_ASYNC16(smem_u32(&Ws[p][srow][skq]),     Wptr + ks + skq);
            CP_ASYNC16(smem_u32(&Ws[p][srow][skq + 4]), Wptr + ks + skq + 4);
        }
        CP_COMMIT();         // commit (possibly empty) to keep group count uniform

        // compute slab s: 2 k8 chunks
#pragma unroll
        for (int ck = 0; ck < 2; ck++) {
            const int kk = ck * 8;
            uint32_t a[4][4];
#pragma unroll
            for (int mt = 0; mt < 4; mt++) {
                int r = m0w + mt * 16 + gid;
                a[mt][0] = __float_as_uint(As[cur][r][kk + tig]);
                a[mt][1] = __float_as_uint(As[cur][r + 8][kk + tig]);
                a[mt][2] = __float_as_uint(As[cur][r][kk + tig + 4]);
                a[mt][3] = __float_as_uint(As[cur][r + 8][kk + tig + 4]);
            }
            uint32_t bfr[4][2];
#pragma unroll
            for (int nt = 0; nt < 4; nt++) {
                int n = n0w + nt * 8 + gid;
                bfr[nt][0] = __float_as_uint(Ws[cur][n][kk + tig]);
                bfr[nt][1] = __float_as_uint(Ws[cur][n][kk + tig + 4]);
            }
#pragma unroll
            for (int mt = 0; mt < 4; mt++)
#pragma unroll
                for (int nt = 0; nt < 4; nt++)
                    mma_tf32(c[mt][nt][0], c[mt][nt][1], c[mt][nt][2], c[mt][nt][3],
                             a[mt][0], a[mt][1], a[mt][2], a[mt][3],
                             bfr[nt][0], bfr[nt][1]);
        }
    }

#pragma unroll
    for (int mt = 0; mt < 4; mt++) {
        const size_t r0 = mbase + m0w + mt * 16 + gid;
#pragma unroll
        for (int nt = 0; nt < 4; nt++) {
            const int col = n0w + nt * 8 + 2 * tig;
            *(float2*)(g_xi + r0 * 128 + col)       = make_float2(c[mt][nt][0], c[mt][nt][1]);
            *(float2*)(g_xi + (r0 + 8) * 128 + col) = make_float2(c[mt][nt][2], c[mt][nt][3]);
        }
    }
}

// ---------------------------------------------------------------------------
// Kernel 3: layer-2 recurrent scan + reverse step + MLP head.  (unchanged)
// ---------------------------------------------------------------------------
__global__ __launch_bounds__(256, 1)
void lstm2_scan_kernel(const float* __restrict__ whh2f,
                       const float* __restrict__ wih2r, const float* __restrict__ b2r,
                       const float* __restrict__ w_fc1, const float* __restrict__ b_fc1,
                       const float* __restrict__ w_out, const float* __restrict__ b_out,
                       float* __restrict__ out)
{
    const int b0  = blockIdx.x * 8;
    const int tid = threadIdx.x;
    const int w   = tid >> 5;
    const int j   = tid & 31;
    const int bb  = b0 + w;

    __shared__ float shh[8][32];
    __shared__ float h1last[8][128];
    __shared__ float zrev[8][128];
    __shared__ float slast[8][64];
    __shared__ float sfc[8][64];

    ull wq[4][16];
#pragma unroll
    for (int q = 0; q < 4; q++) {
        const ull* wr = (const ull*)(whh2f + (q * 32 + j) * H2);
#pragma unroll
        for (int p = 0; p < 16; p++) wq[q][p] = wr[p];
    }

    shh[w][j] = 0.f;
    float c = 0.f, hmine = 0.f;

    const float* xibase = g_xi + (size_t)bb * 128 + j;
    float xin[4];
#pragma unroll
    for (int q = 0; q < 4; q++) xin[q] = xibase[q * 32];

    __syncwarp();

    for (int t = 0; t < TT; ++t) {
        float xnx[4] = {0.f, 0.f, 0.f, 0.f};
        if (t + 1 < TT) {
            const float* p = xibase + (size_t)(t + 1) * BB * 128;
#pragma unroll
            for (int q = 0; q < 4; q++) xnx[q] = p[q * 32];
        }

        ull acc[4];
#pragma unroll
        for (int q = 0; q < 4; q++) acc[q] = pack2(xin[q], 0.f);

#pragma unroll
        for (int p = 0; p < 16; p++) {
            ull hv = *(const ull*)&shh[w][2 * p];
#pragma unroll
            for (int q = 0; q < 4; q++) ffma2(acc[q], hv, wq[q][p]);
        }
        float zi = hadd2(acc[0]);
        float zf = hadd2(acc[1]);
        float zg = hadd2(acc[2]);
        float zo = hadd2(acc[3]);
        c = sigm(zf) * c + sigm(zi) * tanh_(zg);
        hmine = sigm(zo) * tanh_(c);

        __syncwarp();
        shh[w][j] = hmine;
        __syncwarp();

#pragma unroll
        for (int q = 0; q < 4; q++) xin[q] = xnx[q];
    }

    __syncthreads();

    {
        int idx = tid * 4;
        int b = idx >> 7, k = idx & 127;
        *(float4*)&h1last[b][k] =
            *(const float4*)(g_h1 + ((size_t)(TT - 1) * BB + b0 + b) * 128 + k);
    }
    __syncthreads();

    {
        const int g2 = tid & 127;
        const int hf = tid >> 7;
        const float brv = b2r[g2];
        float a[4] = {brv, brv, brv, brv};
        const float* wr = wih2r + g2 * G2;
        for (int k = 0; k < G2; k++) {
            float wv = __ldg(wr + k);
#pragma unroll
            for (int b = 0; b < 4; b++)
                a[b] = fmaf(h1last[hf * 4 + b][k], wv, a[b]);
        }
#pragma unroll
        for (int b = 0; b < 4; b++) zrev[hf * 4 + b][g2] = a[b];
    }
    __syncthreads();
    {
        const int b = tid >> 5, jj = tid & 31;
        float zi = zrev[b][jj];
        float zg = zrev[b][64 + jj], zo = zrev[b][96 + jj];
        float cr = sigm(zi) * tanh_(zg);
        float hr = sigm(zo) * tanh_(cr);
        slast[b][jj]      = shh[b][jj];
        slast[b][32 + jj] = hr;
    }
    __syncthreads();

#pragma unroll
    for (int rep = 0; rep < 2; rep++) {
        int item = tid + rep * 256;
        int b = item >> 6, o = item & 63;
        float a = b_fc1[o];
        const float* wf = w_fc1 + o * 64;
        for (int k = 0; k < 64; k++) a = fmaf(slast[b][k], __ldg(wf + k), a);
        sfc[b][o] = fmaxf(a, 0.f);
    }
    __syncthreads();

    if (tid < 8) {
        float a = b_out[0];
        for (int k = 0; k < 64; k++) a = fmaf(sfc[tid][k], __ldg(w_out + k), a);
        out[b0 + tid] = sigm(a);
    }
}

// ---------------------------------------------------------------------------
extern "C" void kernel_launch(void* const* d_in, const int* in_sizes, int n_in,
                              void* d_out, int out_size)
{
    (void)in_sizes; (void)n_in; (void)out_size;
    const float* x     = (const float*)d_in[0];
    const float* wih1f = (const float*)d_in[1];
    const float* whh1f = (const float*)d_in[2];
    const float* b1f   = (const float*)d_in[3];
    const float* wih1r = (const float*)d_in[4];
    const float* whh1r = (const float*)d_in[5];
    const float* b1r   = (const float*)d_in[6];
    const float* wih2f = (const float*)d_in[7];
    const float* whh2f = (const float*)d_in[8];
    const float* b2f   = (const float*)d_in[9];
    const float* wih2r = (const float*)d_in[10];
    const float* b2r   = (const float*)d_in[12];
    const float* w_fc1 = (const float*)d_in[13];
    const float* b_fc1 = (const float*)d_in[14];
    const float* w_out = (const float*)d_in[15];
    const float* b_out = (const float*)d_in[16];
    float* out = (float*)d_out;

    // idempotent, executes immediately (not a stream op) — graph-capture safe
    cudaFuncSetAttribute(xi_gemm_tc,
                         cudaFuncAttributeMaxDynamicSharedMemorySize, XI_SMEM_BYTES);

    lstm1_tc<<<dim3(BB / 16, 2), 256>>>(x, wih1f, whh1f, b1f, wih1r, whh1r, b1r);
    xi_gemm_tc<<<(TT * BB) / 128, 256, XI_SMEM_BYTES>>>(wih2f, b2f);
    lstm2_scan_kernel<<<BB / 8, 256>>>(whh2f, wih2r, b2r,
                                       w_fc1, b_fc1, w_out, b_out, out);
}

// round 14
// speedup vs baseline: 3.6368x; 1.2951x over previous
#include <cuda_runtime.h>
#include <cstdint>

#define TT   512
#define BB   1024
#define H1   64
#define H2   32
#define G2   128     // 4*H2

typedef unsigned long long ull;

// scratch: h1[t][b][j] (values tf32-rounded), j in [0,128): fwd [0,64), rev [64,128)
__device__ float g_h1[(size_t)TT * BB * 128];

// ---- fast activations -----------------------------------------------------
__device__ __forceinline__ float tanh_(float x) {
    float y;
    asm("tanh.approx.f32 %0, %1;" : "=f"(y) : "f"(x));
    return y;
}
__device__ __forceinline__ float sigm(float x) {
    return fmaf(tanh_(x * 0.5f), 0.5f, 0.5f);
}

// ---- tf32 / mma helpers -----------------------------------------------------
__device__ __forceinline__ uint32_t to_tf32(float x) {
    uint32_t r;
    asm("cvt.rna.tf32.f32 %0, %1;" : "=r"(r) : "f"(x));
    return r;
}
__device__ __forceinline__ void mma_tf32(float& c0, float& c1, float& c2, float& c3,
                                         uint32_t a0, uint32_t a1, uint32_t a2, uint32_t a3,
                                         uint32_t b0, uint32_t b1) {
    asm("mma.sync.aligned.m16n8k8.row.col.f32.tf32.tf32.f32 "
        "{%0,%1,%2,%3}, {%4,%5,%6,%7}, {%8,%9}, {%0,%1,%2,%3};"
        : "+f"(c0), "+f"(c1), "+f"(c2), "+f"(c3)
        : "r"(a0), "r"(a1), "r"(a2), "r"(a3), "r"(b0), "r"(b1));
}

// ---- cp.async helpers -------------------------------------------------------
__device__ __forceinline__ uint32_t smem_u32(const void* p) {
    return (uint32_t)__cvta_generic_to_shared(p);
}
#define CP_ASYNC16(dst, src) \
    asm volatile("cp.async.ca.shared.global [%0], [%1], 16;" :: "r"(dst), "l"(src))
#define CP_COMMIT() asm volatile("cp.async.commit_group;")
#define CP_WAIT(n)  asm volatile("cp.async.wait_group %0;" :: "n"(n))

// ---------------------------------------------------------------------------
// Kernel 1: bidirectional layer-1 LSTM via tf32 tensor cores.
// grid = (64, 2), block = 256 (8 warps), 16 batches/block.
// Single barrier/step; mma accumulation split into two 4-deep chains.
// h1 is stored tf32-rounded so downstream consumers need no conversion.
// ---------------------------------------------------------------------------
__global__ __launch_bounds__(256, 1)
void lstm1_tc(const float* __restrict__ x,
              const float* __restrict__ wih_f, const float* __restrict__ whh_f,
              const float* __restrict__ b_f,
              const float* __restrict__ wih_r, const float* __restrict__ whh_r,
              const float* __restrict__ b_r)
{
    const int dir  = blockIdx.y;
    const int b0   = blockIdx.x * 16;
    const int tid  = threadIdx.x;
    const int w    = tid >> 5;
    const int lane = tid & 31;
    const int gid  = lane >> 2;          // 0..7
    const int tig  = lane & 3;

    const float* wih = dir ? wih_r : wih_f;
    const float* whh = dir ? whh_r : whh_f;
    const float* bb  = dir ? b_r  : b_f;

    __shared__ float    sxc[16][64];     // 4 KB x chunk
    __shared__ uint32_t hs[2][16][68];   // double-buffered tf32 h

    // Whh B-fragments in registers: [gate q][k-chunk][2]
    uint32_t bf[4][8][2];
#pragma unroll
    for (int q = 0; q < 4; q++) {
        const int row = 64 * q + 8 * w + gid;
#pragma unroll
        for (int kc = 0; kc < 8; kc++) {
            bf[q][kc][0] = to_tf32(whh[row * 64 + 8 * kc + tig]);
            bf[q][kc][1] = to_tf32(whh[row * 64 + 8 * kc + tig + 4]);
        }
    }
    const int cell0 = 8 * w + 2 * tig;
    float wi[4][2], bs4[4][2];
#pragma unroll
    for (int q = 0; q < 4; q++) {
        wi[q][0]  = wih[64 * q + cell0];
        wi[q][1]  = wih[64 * q + cell0 + 1];
        bs4[q][0] = bb[64 * q + cell0];
        bs4[q][1] = bb[64 * q + cell0 + 1];
    }

    for (int i = tid; i < 16 * 68; i += 256) ((uint32_t*)hs[0])[i] = 0u;

    float cc[4] = {0.f, 0.f, 0.f, 0.f};

    __syncthreads();

    for (int tt = 0; tt < TT; ++tt) {
        const int t   = dir ? (TT - 1 - tt) : tt;
        const int cur = tt & 1;
        const int nxt = 1 - cur;

        if ((tt & 63) == 0) {
            const int tbase = dir ? (448 - tt) : tt;
            for (int i = tid; i < 16 * 64; i += 256) {
                int b = i >> 6, to = i & 63;
                sxc[b][to] = x[(size_t)(b0 + b) * TT + tbase + to];
            }
            __syncthreads();
        }
        const int ts = t & 63;

        const float xv0 = sxc[gid][ts];
        const float xv1 = sxc[gid + 8][ts];
        float c[4][4], c2[4][4];
#pragma unroll
        for (int q = 0; q < 4; q++) {
            c[q][0] = fmaf(xv0, wi[q][0], bs4[q][0]);
            c[q][1] = fmaf(xv0, wi[q][1], bs4[q][1]);
            c[q][2] = fmaf(xv1, wi[q][0], bs4[q][0]);
            c[q][3] = fmaf(xv1, wi[q][1], bs4[q][1]);
            c2[q][0] = 0.f; c2[q][1] = 0.f; c2[q][2] = 0.f; c2[q][3] = 0.f;
        }

        // two independent 4-deep accumulation chains
#pragma unroll
        for (int kc = 0; kc < 4; kc++) {
            uint32_t a0 = hs[cur][gid][8 * kc + tig];
            uint32_t a1 = hs[cur][gid + 8][8 * kc + tig];
            uint32_t a2 = hs[cur][gid][8 * kc + tig + 4];
            uint32_t a3 = hs[cur][gid + 8][8 * kc + tig + 4];
            uint32_t e0 = hs[cur][gid][8 * (kc + 4) + tig];
            uint32_t e1 = hs[cur][gid + 8][8 * (kc + 4) + tig];
            uint32_t e2 = hs[cur][gid][8 * (kc + 4) + tig + 4];
            uint32_t e3 = hs[cur][gid + 8][8 * (kc + 4) + tig + 4];
#pragma unroll
            for (int q = 0; q < 4; q++) {
                mma_tf32(c[q][0], c[q][1], c[q][2], c[q][3],
                         a0, a1, a2, a3, bf[q][kc][0], bf[q][kc][1]);
                mma_tf32(c2[q][0], c2[q][1], c2[q][2], c2[q][3],
                         e0, e1, e2, e3, bf[q][kc + 4][0], bf[q][kc + 4][1]);
            }
        }
#pragma unroll
        for (int q = 0; q < 4; q++) {
            c[q][0] += c2[q][0]; c[q][1] += c2[q][1];
            c[q][2] += c2[q][2]; c[q][3] += c2[q][3];
        }

        // cell update, register-resident; produce tf32-rounded h
        uint32_t ht[4];
#pragma unroll
        for (int j = 0; j < 4; j++) {
            float zi = c[0][j], zf = c[1][j], zg = c[2][j], zo = c[3][j];
            cc[j] = sigm(zf) * cc[j] + sigm(zi) * tanh_(zg);
            ht[j] = to_tf32(sigm(zo) * tanh_(cc[j]));
        }

        hs[nxt][gid][cell0]         = ht[0];
        hs[nxt][gid][cell0 + 1]     = ht[1];
        hs[nxt][gid + 8][cell0]     = ht[2];
        hs[nxt][gid + 8][cell0 + 1] = ht[3];

        *(float2*)&g_h1[((size_t)t * BB + b0 + gid) * 128 + dir * 64 + cell0] =
            make_float2(__uint_as_float(ht[0]), __uint_as_float(ht[1]));
        *(float2*)&g_h1[((size_t)t * BB + b0 + gid + 8) * 128 + dir * 64 + cell0] =
            make_float2(__uint_as_float(ht[2]), __uint_as_float(ht[3]));

        __syncthreads();   // single barrier per step
    }
}

// ---------------------------------------------------------------------------
// Kernel 2 (FUSED): layer-2 forward scan with in-kernel input projection
// via tf32 tensor cores, + single reverse step + MLP head.  No xi buffer.
// grid = 128, block = 256 (8 warps), 8 batches/block.
// Per step: z[8(m16),128] = [h1[t] | h2] (k=160) @ Wcat^T, Wcat frags in regs.
// h1 tiles stream via 4-deep cp.async ring (4 KB/step, 4-step lookahead).
// ---------------------------------------------------------------------------
__global__ __launch_bounds__(256, 1)
void lstm2_fused(const float* __restrict__ wih2f, const float* __restrict__ whh2f,
                 const float* __restrict__ b2f,
                 const float* __restrict__ wih2r, const float* __restrict__ b2r,
                 const float* __restrict__ w_fc1, const float* __restrict__ b_fc1,
                 const float* __restrict__ w_out, const float* __restrict__ b_out,
                 float* __restrict__ out)
{
    const int b0   = blockIdx.x * 8;
    const int tid  = threadIdx.x;
    const int w    = tid >> 5;
    const int lane = tid & 31;
    const int gid  = lane >> 2;          // 0..7 (batch row)
    const int tig  = lane & 3;

    __shared__ uint32_t hst[4][8][132];  // h1 tile ring (fp32 bits, tf32-valued)
    __shared__ uint32_t hh2[2][8][36];   // h2 tf32, double-buffered
    __shared__ float    zbuf[8][132];    // gate pre-activations (no bias)
    __shared__ float    slast[8][64];
    __shared__ float    sfc[8][64];

    // Wcat B-fragments in registers: warp owns gates [16w, 16w+16) = 2 n-tiles.
    // k = 160: [0,128) -> wih2f, [128,160) -> whh2f.  Raw fp32 bits (HW truncates).
    uint32_t wb[2][20][2];
#pragma unroll
    for (int nt = 0; nt < 2; nt++) {
        const int n = 16 * w + 8 * nt + gid;
#pragma unroll
        for (int kc = 0; kc < 20; kc++) {
            const int k0 = 8 * kc + tig;
            const int k1 = k0 + 4;
            float f0 = (k0 < 128) ? wih2f[n * 128 + k0] : whh2f[n * 32 + k0 - 128];
            float f1 = (k1 < 128) ? wih2f[n * 128 + k1] : whh2f[n * 32 + k1 - 128];
            wb[nt][kc][0] = __float_as_uint(f0);
            wb[nt][kc][1] = __float_as_uint(f1);
        }
    }

    // cell-phase constants: thread -> (batch cb, cell cj)
    const int cb = tid >> 5;
    const int cj = tid & 31;
    const float bi  = b2f[cj];
    const float bff = b2f[32 + cj];
    const float bgg = b2f[64 + cj];
    const float boo = b2f[96 + cj];
    float cstate = 0.f;
    float hlast  = 0.f;                  // fp32 copy of final forward h2

    // zero h2 buffers
    for (int i = tid; i < 2 * 8 * 36; i += 256) ((uint32_t*)hh2)[i] = 0u;

    // staging role: thread stages batch sb, 4 floats at col sk
    const int sb = tid >> 5;
    const int sk = (tid & 31) * 4;

    // prologue: issue tiles t=0..2
#pragma unroll
    for (int p = 0; p < 3; p++) {
        CP_ASYNC16(smem_u32(&hst[p][sb][sk]),
                   g_h1 + ((size_t)p * BB + b0 + sb) * 128 + sk);
        CP_COMMIT();
    }

    for (int t = 0; t < TT; ++t) {
        const int cur = t & 3;
        const int hb  = t & 1;

        CP_WAIT(2);          // tile t complete
        __syncthreads();     // + hh2/zbuf handoff from previous step

        if (t + 3 < TT) {
            CP_ASYNC16(smem_u32(&hst[(t + 3) & 3][sb][sk]),
                       g_h1 + ((size_t)(t + 3) * BB + b0 + sb) * 128 + sk);
        }
        CP_COMMIT();

        // z = [h1 | h2] @ Wcat^T  (m rows 8-15 are zero via a1=a3=0)
        float c[2][4] = {{0.f, 0.f, 0.f, 0.f}, {0.f, 0.f, 0.f, 0.f}};
#pragma unroll
        for (int kc = 0; kc < 16; kc++) {
            uint32_t a0 = hst[cur][gid][8 * kc + tig];
            uint32_t a2 = hst[cur][gid][8 * kc + tig + 4];
            mma_tf32(c[0][0], c[0][1], c[0][2], c[0][3],
                     a0, 0u, a2, 0u, wb[0][kc][0], wb[0][kc][1]);
            mma_tf32(c[1][0], c[1][1], c[1][2], c[1][3],
                     a0, 0u, a2, 0u, wb[1][kc][0], wb[1][kc][1]);
        }
#pragma unroll
        for (int kc = 16; kc < 20; kc++) {
            uint32_t a0 = hh2[hb][gid][8 * (kc - 16) + tig];
            uint32_t a2 = hh2[hb][gid][8 * (kc - 16) + tig + 4];
            mma_tf32(c[0][0], c[0][1], c[0][2], c[0][3],
                     a0, 0u, a2, 0u, wb[0][kc][0], wb[0][kc][1]);
            mma_tf32(c[1][0], c[1][1], c[1][2], c[1][3],
                     a0, 0u, a2, 0u, wb[1][kc][0], wb[1][kc][1]);
        }

        // park z fragments (rows 0-7 only)
        *(float2*)&zbuf[gid][16 * w + 2 * tig]     = make_float2(c[0][0], c[0][1]);
        *(float2*)&zbuf[gid][16 * w + 8 + 2 * tig] = make_float2(c[1][0], c[1][1]);
        __syncthreads();

        // cell update
        {
            float zi = zbuf[cb][cj]      + bi;
            float zf = zbuf[cb][32 + cj] + bff;
            float zg = zbuf[cb][64 + cj] + bgg;
            float zo = zbuf[cb][96 + cj] + boo;
            cstate = sigm(zf) * cstate + sigm(zi) * tanh_(zg);
            float h = sigm(zo) * tanh_(cstate);
            hlast = h;
            hh2[1 - hb][cb][cj] = to_tf32(h);
        }
        // next iteration's top barrier orders hh2/zbuf handoff
    }

    __syncthreads();
    // hst[3] = h1[T-1] tile (issued at t=508, untouched since).

    // layer-2 reverse: single step at t = T-1 from h=c=0
    {
        const int g2 = tid & 127;
        const int hf = tid >> 7;
        const float brv = b2r[g2];
        float a[4] = {brv, brv, brv, brv};
        const float* wr = wih2r + g2 * G2;
        for (int k = 0; k < G2; k++) {
            float wv = __ldg(wr + k);
#pragma unroll
            for (int b = 0; b < 4; b++)
                a[b] = fmaf(__uint_as_float(hst[3][hf * 4 + b][k]), wv, a[b]);
        }
#pragma unroll
        for (int b = 0; b < 4; b++) zbuf[hf * 4 + b][g2] = a[b];
    }
    __syncthreads();
    {
        float zi = zbuf[cb][cj];
        float zg = zbuf[cb][64 + cj], zo = zbuf[cb][96 + cj];
        float cr = sigm(zi) * tanh_(zg);      // c_prev = 0
        float hr = sigm(zo) * tanh_(cr);
        slast[cb][cj]      = hlast;           // fp32 forward h2
        slast[cb][32 + cj] = hr;
    }
    __syncthreads();

    // fc1 (64x64) + relu: 512 items, 2 per thread
#pragma unroll
    for (int rep = 0; rep < 2; rep++) {
        int item = tid + rep * 256;
        int b = item >> 6, o = item & 63;
        float a = b_fc1[o];
        const float* wf = w_fc1 + o * 64;
        for (int k = 0; k < 64; k++) a = fmaf(slast[b][k], __ldg(wf + k), a);
        sfc[b][o] = fmaxf(a, 0.f);
    }
    __syncthreads();

    if (tid < 8) {
        float a = b_out[0];
        for (int k = 0; k < 64; k++) a = fmaf(sfc[tid][k], __ldg(w_out + k), a);
        out[b0 + tid] = sigm(a);
    }
}

// ---------------------------------------------------------------------------
extern "C" void kernel_launch(void* const* d_in, const int* in_sizes, int n_in,
                              void* d_out, int out_size)
{
    (void)in_sizes; (void)n_in; (void)out_size;
    const float* x     = (const float*)d_in[0];
    const float* wih1f = (const float*)d_in[1];
    const float* whh1f = (const float*)d_in[2];
    const float* b1f   = (const float*)d_in[3];
    const float* wih1r = (const float*)d_in[4];
    const float* whh1r = (const float*)d_in[5];
    const float* b1r   = (const float*)d_in[6];
    const float* wih2f = (const float*)d_in[7];
    const float* whh2f = (const float*)d_in[8];
    const float* b2f   = (const float*)d_in[9];
    const float* wih2r = (const float*)d_in[10];
    const float* b2r   = (const float*)d_in[12];
    const float* w_fc1 = (const float*)d_in[13];
    const float* b_fc1 = (const float*)d_in[14];
    const float* w_out = (const float*)d_in[15];
    const float* b_out = (const float*)d_in[16];
    float* out = (float*)d_out;

    lstm1_tc<<<dim3(BB / 16, 2), 256>>>(x, wih1f, whh1f, b1f, wih1r, whh1r, b1r);
    lstm2_fused<<<BB / 8, 256>>>(wih2f, whh2f, b2f, wih2r, b2r,
                                 w_fc1, b_fc1, w_out, b_out, out);
}